// round 10
// baseline (speedup 1.0000x reference)
#include <cuda_runtime.h>
#include <cuda_fp16.h>
#include <cstdint>
#include <cstddef>

#define BB 16
#define TT 512
#define DD 256
#define HH 256
#define GG 1024
#define NTOT 65536
#define SCALE_ 0.1f

// ---------------- scratch (device globals, no cudaMalloc) ----------------
__device__ float  g_Wx[(size_t)BB * TT * GG];        // 32 MB
__device__ __half g_Vh[(size_t)BB * TT * NTOT];      // 1 GB fp16 V
__device__ __half g_xh[(size_t)BB * TT * DD];        // 4 MB  x in half
__device__ __half g_Bh[(size_t)HH * HH * DD];        // 32 MB B_w as [o][h'][d]

// ---------------- helpers ----------------
__device__ __forceinline__ uint32_t smem_u32(const void* p) {
    return (uint32_t)__cvta_generic_to_shared(p);
}
__device__ __forceinline__ void cp16s(uint32_t dst, const void* src) {
    asm volatile("cp.async.cg.shared.global [%0], [%1], 16;" :: "r"(dst), "l"(src));
}
__device__ __forceinline__ void ldsm4(uint32_t* r, uint32_t a) {
    asm volatile("ldmatrix.sync.aligned.m8n8.x4.shared.b16 {%0,%1,%2,%3}, [%4];"
        : "=r"(r[0]), "=r"(r[1]), "=r"(r[2]), "=r"(r[3]) : "r"(a));
}
__device__ __forceinline__ void mma16816(float* d, const uint32_t* a, const uint32_t* b) {
    asm volatile(
        "mma.sync.aligned.m16n8k16.row.col.f32.f16.f16.f32 "
        "{%0,%1,%2,%3}, {%4,%5,%6,%7}, {%8,%9}, {%0,%1,%2,%3};\n"
        : "+f"(d[0]), "+f"(d[1]), "+f"(d[2]), "+f"(d[3])
        : "r"(a[0]), "r"(a[1]), "r"(a[2]), "r"(a[3]), "r"(b[0]), "r"(b[1]));
}
// store a float into the same smem offset of cluster CTA `rank`
#define ST_CL_F32(laddr, rank, val)                                          \
    asm volatile("{\n\t.reg .b32 ra;\n\t"                                    \
                 "mapa.shared::cluster.u32 ra, %0, %1;\n\t"                  \
                 "st.shared::cluster.f32 [ra], %2;\n\t}"                     \
                 :: "r"(laddr), "r"(rank), "f"(val) : "memory")
// release-arrive on the mbarrier at the same smem offset in cluster CTA `rank`
#define MBAR_ARRIVE_CL(laddr, rank)                                          \
    asm volatile("{\n\t.reg .b32 ra;\n\t"                                    \
                 "mapa.shared::cluster.u32 ra, %0, %1;\n\t"                  \
                 "mbarrier.arrive.release.cluster.shared::cluster.b64 _, [ra];\n\t}" \
                 :: "r"(laddr), "r"(rank) : "memory")
// acquire(cluster) parity wait on local mbarrier
#define MBWAIT_CL(a, ph) do {                                                \
    asm volatile("{\n\t.reg .pred P1;\n\t"                                   \
        "WL_%=:\n\t"                                                         \
        "mbarrier.try_wait.parity.acquire.cluster.shared::cta.b64 P1, [%0], %1, 0x989680;\n\t" \
        "@P1 bra.uni WD_%=;\n\t"                                             \
        "bra.uni WL_%=;\n\t"                                                 \
        "WD_%=:\n\t}"                                                        \
        :: "r"(a), "r"(ph) : "memory");                                      \
} while (0)

__device__ __forceinline__ float fsigm(float x) {
    return __fdividef(1.f, 1.f + __expf(-x));
}
__device__ __forceinline__ float ftanh(float x) {
    return __fdividef(2.f, 1.f + __expf(-2.f * x)) - 1.f;
}

// ---------------- prep: x -> half ----------------
__global__ void conv_x_kernel(const float2* __restrict__ src) {
    __half2* dst = (__half2*)g_xh;
    const int n2 = BB * TT * DD / 2;
    for (int i = blockIdx.x * blockDim.x + threadIdx.x; i < n2;
         i += gridDim.x * blockDim.x) {
        float2 v = src[i];
        dst[i] = __floats2half2_rn(v.x, v.y);
    }
}

// ---------------- prep: B_w [o][d][h] f32 -> g_Bh [o][h][d] half ----------------
__global__ void transB_kernel(const float* __restrict__ Bw) {
    __shared__ float tile[32][33];
    const int o  = blockIdx.z;
    const int d0 = blockIdx.y * 32;
    const int h0 = blockIdx.x * 32;
    const int tx = threadIdx.x, ty = threadIdx.y;
    const float* src = Bw + (size_t)o * NTOT;
#pragma unroll
    for (int i = 0; i < 4; i++)
        tile[ty + i * 8][tx] = src[(size_t)(d0 + ty + i * 8) * HH + h0 + tx];
    __syncthreads();
    __half* dst = g_Bh + (size_t)o * NTOT;
#pragma unroll
    for (int i = 0; i < 4; i++)
        dst[(size_t)(h0 + ty + i * 8) * DD + d0 + tx] =
            __float2half_rn(tile[tx][ty + i * 8]);
}

// ===========================================================================
// HMMA V GEMM (unchanged: 855us, tensor 52.8%).
// ===========================================================================
#define VBM 256
#define VBN 128
#define ASTG (VBM * 128)
#define BSTG (VBN * 128)
#define STG  (ASTG + BSTG)
#define VSMEM (3 * STG)

__global__ void __launch_bounds__(256, 1) gemm_v_mma(void) {
    extern __shared__ char smem[];
    const uint32_t sb = smem_u32(smem);
    const int tid  = threadIdx.x;
    const int lane = tid & 31;
    const int w    = tid >> 5;

    const int m0 = blockIdx.x * VBM;
    const int n0 = blockIdx.y * VBN;
    const __half* Ag = g_xh + (size_t)m0 * DD;
    const __half* Bg = g_Bh + (size_t)n0 * DD;

    const int wm = (w & 3) * 64;
    const int wn = (w >> 2) * 64;

    const int a_row = wm + (lane & 15);
    const int a_rx  = ((a_row & 7) * 16);
    const int a_xo  = ((lane >> 4) & 1) * 16;
    const int b_row = wn + (lane & 7) + ((lane >> 4) & 1) * 8;
    const int b_rx  = ((b_row & 7) * 16);
    const int b_xo  = ((lane >> 3) & 1) * 16;

    float acc[4][8][4];
#pragma unroll
    for (int i = 0; i < 4; i++)
#pragma unroll
        for (int j = 0; j < 8; j++)
#pragma unroll
            for (int e = 0; e < 4; e++) acc[i][j][e] = 0.f;

    auto load_stage = [&](int kc, int stg) {
        const uint32_t sA = sb + stg * STG;
        const uint32_t sB = sA + ASTG;
        const __half* As = Ag + kc * 64;
        const __half* Bs2 = Bg + kc * 64;
#pragma unroll
        for (int i = 0; i < 8; i++) {
            const int idx = tid + 256 * i;
            const int r = idx >> 3, c = idx & 7;
            const uint32_t d = r * 128 + ((c * 16) ^ ((r & 7) * 16));
            cp16s(sA + d, As + (size_t)r * DD + c * 8);
        }
#pragma unroll
        for (int i = 0; i < 4; i++) {
            const int idx = tid + 256 * i;
            const int r = idx >> 3, c = idx & 7;
            const uint32_t d = r * 128 + ((c * 16) ^ ((r & 7) * 16));
            cp16s(sB + d, Bs2 + (size_t)r * DD + c * 8);
        }
        asm volatile("cp.async.commit_group;");
    };

    load_stage(0, 0);
    load_stage(1, 1);

#pragma unroll
    for (int kc = 0; kc < 4; kc++) {
        if (kc < 3) asm volatile("cp.async.wait_group 1;");
        else        asm volatile("cp.async.wait_group 0;");
        __syncthreads();
        if (kc < 2) load_stage(kc + 2, (kc + 2) % 3);

        const uint32_t sA = sb + (kc % 3) * STG;
        const uint32_t sB = sA + ASTG;
#pragma unroll
        for (int ks = 0; ks < 4; ks++) {
            uint32_t afr[4][4], bfr[4][4];
#pragma unroll
            for (int mt = 0; mt < 4; mt++) {
                const int r = a_row + mt * 16;
                ldsm4(afr[mt], sA + r * 128 + ((ks * 32 + a_xo) ^ a_rx));
            }
#pragma unroll
            for (int nt2 = 0; nt2 < 4; nt2++) {
                const int r = b_row + nt2 * 16;
                ldsm4(bfr[nt2], sB + r * 128 + ((ks * 32 + b_xo) ^ b_rx));
            }
#pragma unroll
            for (int mt = 0; mt < 4; mt++)
#pragma unroll
                for (int nt = 0; nt < 8; nt++)
                    mma16816(acc[mt][nt], afr[mt], &bfr[nt >> 1][(nt & 1) * 2]);
        }
        __syncthreads();
    }

    const int fr = lane >> 2, fq = (lane & 3) * 2;
#pragma unroll
    for (int mt = 0; mt < 4; mt++) {
        const int mA = m0 + wm + mt * 16 + fr;
#pragma unroll
        for (int nt = 0; nt < 8; nt++) {
            const int col = n0 + wn + nt * 8 + fq;
            *(__half2*)&g_Vh[(size_t)mA * NTOT + col] =
                __floats2half2_rn(acc[mt][nt][0], acc[mt][nt][1]);
            *(__half2*)&g_Vh[(size_t)(mA + 8) * NTOT + col] =
                __floats2half2_rn(acc[mt][nt][2], acc[mt][nt][3]);
        }
    }
}

// ===========================================================================
// GEMM 2 (fp32 SIMT): Wx = x @ W^T + b  (unchanged)
// ===========================================================================
__global__ __launch_bounds__(256) void gemm_wx_kernel(
    const float* __restrict__ A, const float* __restrict__ Ww,
    const float* __restrict__ Wb)
{
    __shared__ float As[2][16 * 132];
    __shared__ float Bs[2][16 * 132];
    const int tid = threadIdx.x;
    const int n0  = blockIdx.x * 128;
    const int m0  = blockIdx.y * 128;
    const int am = tid >> 1, ah = (tid & 1) * 8;
    const int tx = tid & 15, ty = tid >> 4;
    const float* Aptr = A  + (size_t)(m0 + am) * DD + ah;
    const float* Wptr = Ww + (size_t)(n0 + am) * DD + ah;

    float4 a0r = *(const float4*)(Aptr);
    float4 a1r = *(const float4*)(Aptr + 4);
    float4 b0r = *(const float4*)(Wptr);
    float4 b1r = *(const float4*)(Wptr + 4);

    float acc[8][8];
#pragma unroll
    for (int i = 0; i < 8; i++)
#pragma unroll
        for (int j = 0; j < 8; j++) acc[i][j] = 0.f;

    {
        float av[8] = {a0r.x,a0r.y,a0r.z,a0r.w,a1r.x,a1r.y,a1r.z,a1r.w};
        float bv[8] = {b0r.x,b0r.y,b0r.z,b0r.w,b1r.x,b1r.y,b1r.z,b1r.w};
#pragma unroll
        for (int i = 0; i < 8; i++) {
            As[0][(ah + i) * 132 + am] = av[i];
            Bs[0][(ah + i) * 132 + am] = bv[i];
        }
    }
    __syncthreads();

    int p = 0;
#pragma unroll 1
    for (int s = 0; s < 16; s++) {
        if (s < 15) {
            const int k0 = (s + 1) * 16;
            a0r = *(const float4*)(Aptr + k0);
            a1r = *(const float4*)(Aptr + k0 + 4);
            b0r = *(const float4*)(Wptr + k0);
            b1r = *(const float4*)(Wptr + k0 + 4);
        }
#pragma unroll
        for (int kk = 0; kk < 16; kk++) {
            float4 a0 = *(const float4*)&As[p][kk * 132 + ty * 4];
            float4 a1 = *(const float4*)&As[p][kk * 132 + 64 + ty * 4];
            float4 b0 = *(const float4*)&Bs[p][kk * 132 + tx * 4];
            float4 b1 = *(const float4*)&Bs[p][kk * 132 + 64 + tx * 4];
            float ar[8] = {a0.x,a0.y,a0.z,a0.w,a1.x,a1.y,a1.z,a1.w};
            float br[8] = {b0.x,b0.y,b0.z,b0.w,b1.x,b1.y,b1.z,b1.w};
#pragma unroll
            for (int i = 0; i < 8; i++)
#pragma unroll
                for (int j = 0; j < 8; j++) acc[i][j] += ar[i] * br[j];
        }
        if (s < 15) {
            __syncthreads();
            const int q = p ^ 1;
            float av[8] = {a0r.x,a0r.y,a0r.z,a0r.w,a1r.x,a1r.y,a1r.z,a1r.w};
            float bv[8] = {b0r.x,b0r.y,b0r.z,b0r.w,b1r.x,b1r.y,b1r.z,b1r.w};
#pragma unroll
            for (int i = 0; i < 8; i++) {
                As[q][(ah + i) * 132 + am] = av[i];
                Bs[q][(ah + i) * 132 + am] = bv[i];
            }
            __syncthreads();
            p = q;
        }
    }

    float wb0[4], wb1[4];
#pragma unroll
    for (int j = 0; j < 4; j++) {
        wb0[j] = Wb[n0 + tx * 4 + j];
        wb1[j] = Wb[n0 + 64 + tx * 4 + j];
    }
#pragma unroll
    for (int i = 0; i < 8; i++) {
        const int rr = (i < 4) ? (ty * 4 + i) : (64 + ty * 4 + (i - 4));
        float* Wo = g_Wx + (size_t)(m0 + rr) * GG + n0;
        *(float4*)&Wo[tx * 4] = make_float4(acc[i][0] + wb0[0], acc[i][1] + wb0[1],
                                            acc[i][2] + wb0[2], acc[i][3] + wb0[3]);
        *(float4*)&Wo[64 + tx * 4] = make_float4(acc[i][4] + wb1[0], acc[i][5] + wb1[1],
                                                 acc[i][6] + wb1[2], acc[i][7] + wb1[3]);
    }
}

// ===========================================================================
// Scan v3: 8-CTA cluster per batch. Per-step handoff via DSMEM h push +
// per-CTA mbarrier (count 256 = 32 update threads x 8 CTAs), release-arrive /
// acquire-wait. No cluster barrier in the loop, no L1 flush.
// Max producer skew is 1 phase (local __syncthreads gates our arrivals),
// so parity waits are alias-free.
// ===========================================================================
__global__ void __cluster_dims__(8, 1, 1) __launch_bounds__(512, 1)
scan_kernel(const float* __restrict__ Uw, const float* __restrict__ Ub,
            const float* __restrict__ Bbias, float* __restrict__ out)
{
    __shared__ float h_sm[2][HH];
    __shared__ float gates_sm[128];
    __shared__ float m_sm[32];
    __shared__ float c_sm[32];
    __shared__ float bb_sm[32];
    __shared__ __align__(8) unsigned long long mbar_s;

    const int r     = blockIdx.x;
    const int b     = blockIdx.y;
    const int jbase = r * 32;
    const int t     = threadIdx.x;
    const int qt    = t & 3;
    const int lg    = t >> 2;
    const int row   = (lg >> 5) * HH + jbase + (lg & 31);
    const int r16   = t >> 4;
    const int l16   = t & 15;
    const uint32_t mb = smem_u32(&mbar_s);

    float4 U4[16];
#pragma unroll
    for (int i = 0; i < 16; i++)
        U4[i] = *(const float4*)&Uw[(size_t)row * HH + (size_t)(i * 4 + qt) * 4];
    const float ub = Ub[row];

    if (t < HH)  h_sm[0][t] = 0.f;
    if (t < 32) { c_sm[t] = 0.f; bb_sm[t] = Bbias[jbase + t]; }
    if (t == 0) {
        asm volatile("mbarrier.init.shared.b64 [%0], 256;" :: "r"(mb) : "memory");
    }
    __syncthreads();
    // one-time cluster sync: all mbarriers + h_sm[0] visible before any
    // remote arrive/push
    asm volatile("barrier.cluster.arrive.aligned;" ::: "memory");
    asm volatile("barrier.cluster.wait.aligned;"   ::: "memory");

    const size_t vrow_off = (size_t)(jbase + r16) * HH + (size_t)l16 * 16;
    uint4 v0 = *(const uint4*)(g_Vh + (size_t)(b * TT) * NTOT + vrow_off);
    uint4 v1 = *(const uint4*)(g_Vh + (size_t)(b * TT) * NTOT + vrow_off + 8);
    float wx = (qt == 0) ? g_Wx[(size_t)(b * TT) * GG + row] : 0.f;

    for (int step = 0; step < TT; step++) {
        const int p = step & 1;
        const float4* h4 = (const float4*)h_sm[p];
        const int mrow = b * TT + step;
        const int nrow = (step + 1 < TT) ? (mrow + 1) : mrow;

        // gates: dot(U_row, h), 4 independent accumulator chains
        float ac0 = 0.f, ac1 = 0.f, ac2 = 0.f, ac3 = 0.f;
#pragma unroll
        for (int i = 0; i < 4; i++) {
            float4 h0 = h4[(i * 4 + 0) * 4 + qt];
            float4 u0 = U4[i * 4 + 0];
            ac0 += h0.x * u0.x + h0.y * u0.y + h0.z * u0.z + h0.w * u0.w;
            float4 h1 = h4[(i * 4 + 1) * 4 + qt];
            float4 u1 = U4[i * 4 + 1];
            ac1 += h1.x * u1.x + h1.y * u1.y + h1.z * u1.z + h1.w * u1.w;
            float4 h2 = h4[(i * 4 + 2) * 4 + qt];
            float4 u2 = U4[i * 4 + 2];
            ac2 += h2.x * u2.x + h2.y * u2.y + h2.z * u2.z + h2.w * u2.w;
            float4 h3 = h4[(i * 4 + 3) * 4 + qt];
            float4 u3 = U4[i * 4 + 3];
            ac3 += h3.x * u3.x + h3.y * u3.y + h3.z * u3.z + h3.w * u3.w;
        }
        float acc = (ac0 + ac1) + (ac2 + ac3);
        acc += __shfl_xor_sync(0xffffffffu, acc, 1);
        acc += __shfl_xor_sync(0xffffffffu, acc, 2);

        // m: dot(V_row fp16, h), 2 accumulator chains
        float ma = 0.f, mb2 = 0.f;
        {
            const __half2* vh0 = (const __half2*)&v0;
            const __half2* vh1 = (const __half2*)&v1;
            float4 ha  = h4[l16 * 4 + 0];
            float4 hbv = h4[l16 * 4 + 1];
            float4 hc  = h4[l16 * 4 + 2];
            float4 hd  = h4[l16 * 4 + 3];
            float2 pp;
            pp = __half22float2(vh0[0]); ma  += pp.x * ha.x  + pp.y * ha.y;
            pp = __half22float2(vh0[1]); mb2 += pp.x * ha.z  + pp.y * ha.w;
            pp = __half22float2(vh0[2]); ma  += pp.x * hbv.x + pp.y * hbv.y;
            pp = __half22float2(vh0[3]); mb2 += pp.x * hbv.z + pp.y * hbv.w;
            pp = __half22float2(vh1[0]); ma  += pp.x * hc.x  + pp.y * hc.y;
            pp = __half22float2(vh1[1]); mb2 += pp.x * hc.z  + pp.y * hc.w;
            pp = __half22float2(vh1[2]); ma  += pp.x * hd.x  + pp.y * hd.y;
            pp = __half22float2(vh1[3]); mb2 += pp.x * hd.z  + pp.y * hd.w;
        }
        float macc = ma + mb2;

        // prefetch next step's V and wx (h-independent)
        v0 = *(const uint4*)(g_Vh + (size_t)nrow * NTOT + vrow_off);
        v1 = *(const uint4*)(g_Vh + (size_t)nrow * NTOT + vrow_off + 8);
        float wxn = (qt == 0) ? g_Wx[(size_t)nrow * GG + row] : 0.f;

#pragma unroll
        for (int off = 8; off > 0; off >>= 1)
            macc += __shfl_xor_sync(0xffffffffu, macc, off);

        if (qt == 0)  gates_sm[lg] = acc + wx + ub;
        if (l16 == 0) m_sm[r16] = macc;
        __syncthreads();

        if (t < 32) {
            const int j = jbase + t;
            const float iv = fsigm(gates_sm[t]);
            const float fv = fsigm(gates_sm[32 + t]);
            const float ov = fsigm(gates_sm[64 + t]);
            const float gv = ftanh(gates_sm[96 + t]);
            const float mv = ftanh(m_sm[t] + bb_sm[t]);
            const float c  = fv * c_sm[t] + iv * gv + SCALE_ * mv;
            c_sm[t] = c;
            const float hn = ov * ftanh(c);
            out[((size_t)b * TT + step) * HH + j] = hn;
            if (step == TT - 1) {
                const size_t base = (size_t)BB * TT * HH;
                out[base + (size_t)b * HH + j] = hn;
                out[base + (size_t)BB * HH + (size_t)b * HH + j] = c;
            }
            // push hn into next-step buffer of all 8 cluster CTAs, then
            // release-arrive on each CTA's mbarrier
            const uint32_t la = smem_u32(&h_sm[p ^ 1][j]);
#pragma unroll
            for (int k = 0; k < 8; k++) ST_CL_F32(la, k, hn);
#pragma unroll
            for (int k = 0; k < 8; k++) MBAR_ARRIVE_CL(mb, k);
        }
        wx = wxn;

        // wait for all 256 arrivals of this step (acquire: orders DSMEM pushes)
        MBWAIT_CL(mb, step & 1);
    }
}

// ===========================================================================
// Launcher
// ===========================================================================
extern "C" void kernel_launch(void* const* d_in, const int* in_sizes, int n_in,
                              void* d_out, int out_size)
{
    (void)in_sizes; (void)n_in; (void)out_size;
    const float* x   = (const float*)d_in[0];
    const float* Ww  = (const float*)d_in[1];
    const float* Wb  = (const float*)d_in[2];
    const float* Uw  = (const float*)d_in[3];
    const float* Ub  = (const float*)d_in[4];
    const float* Bw  = (const float*)d_in[5];
    const float* Bb  = (const float*)d_in[6];
    float* out = (float*)d_out;

    cudaFuncSetAttribute(gemm_v_mma,
                         cudaFuncAttributeMaxDynamicSharedMemorySize, VSMEM);

    conv_x_kernel<<<1024, 256>>>((const float2*)x);
    transB_kernel<<<dim3(8, 8, 256), dim3(32, 8)>>>(Bw);
    gemm_wx_kernel<<<dim3(GG / 128, (BB * TT) / 128), 256>>>(x, Ww, Wb);
    gemm_v_mma<<<dim3(8192 / VBM, NTOT / VBN), 256, VSMEM>>>();
    scan_kernel<<<dim3(8, BB), 512>>>(Uw, Ub, Bb, out);
}

// round 11
// speedup vs baseline: 1.3905x; 1.3905x over previous
#include <cuda_runtime.h>
#include <cuda_fp16.h>
#include <cstdint>
#include <cstddef>

#define BB 16
#define TT 512
#define DD 256
#define HH 256
#define GG 1024
#define NTOT 65536
#define SCALE_ 0.1f

// ---------------- scratch (device globals, no cudaMalloc) ----------------
__device__ float  g_Wx[(size_t)BB * TT * GG];        // 32 MB
__device__ __half g_Vh[(size_t)BB * TT * NTOT];      // 1 GB fp16 V
__device__ __half g_xh[(size_t)BB * TT * DD];        // 4 MB  x in half
__device__ __half g_Bh[(size_t)HH * HH * DD];        // 32 MB B_w as [o][h'][d]

// ---------------- helpers ----------------
__device__ __forceinline__ uint32_t smem_u32(const void* p) {
    return (uint32_t)__cvta_generic_to_shared(p);
}
__device__ __forceinline__ void cp16s(uint32_t dst, const void* src) {
    asm volatile("cp.async.cg.shared.global [%0], [%1], 16;" :: "r"(dst), "l"(src));
}
__device__ __forceinline__ void ldsm4(uint32_t* r, uint32_t a) {
    asm volatile("ldmatrix.sync.aligned.m8n8.x4.shared.b16 {%0,%1,%2,%3}, [%4];"
        : "=r"(r[0]), "=r"(r[1]), "=r"(r[2]), "=r"(r[3]) : "r"(a));
}
__device__ __forceinline__ void mma16816(float* d, const uint32_t* a, const uint32_t* b) {
    asm volatile(
        "mma.sync.aligned.m16n8k16.row.col.f32.f16.f16.f32 "
        "{%0,%1,%2,%3}, {%4,%5,%6,%7}, {%8,%9}, {%0,%1,%2,%3};\n"
        : "+f"(d[0]), "+f"(d[1]), "+f"(d[2]), "+f"(d[3])
        : "r"(a[0]), "r"(a[1]), "r"(a[2]), "r"(a[3]), "r"(b[0]), "r"(b[1]));
}
// store a float into the same smem offset of cluster CTA `rank`
#define ST_CL_F32(laddr, rank, val)                                          \
    asm volatile("{\n\t.reg .b32 ra;\n\t"                                    \
                 "mapa.shared::cluster.u32 ra, %0, %1;\n\t"                  \
                 "st.shared::cluster.f32 [ra], %2;\n\t}"                     \
                 :: "r"(laddr), "r"(rank), "f"(val) : "memory")

__device__ __forceinline__ float fsigm(float x) {
    return __fdividef(1.f, 1.f + __expf(-x));
}
__device__ __forceinline__ float ftanh(float x) {
    return __fdividef(2.f, 1.f + __expf(-2.f * x)) - 1.f;
}

// ---------------- prep: x -> half ----------------
__global__ void conv_x_kernel(const float2* __restrict__ src) {
    __half2* dst = (__half2*)g_xh;
    const int n2 = BB * TT * DD / 2;
    for (int i = blockIdx.x * blockDim.x + threadIdx.x; i < n2;
         i += gridDim.x * blockDim.x) {
        float2 v = src[i];
        dst[i] = __floats2half2_rn(v.x, v.y);
    }
}

// ---------------- prep: B_w [o][d][h] f32 -> g_Bh [o][h][d] half ----------------
__global__ void transB_kernel(const float* __restrict__ Bw) {
    __shared__ float tile[32][33];
    const int o  = blockIdx.z;
    const int d0 = blockIdx.y * 32;
    const int h0 = blockIdx.x * 32;
    const int tx = threadIdx.x, ty = threadIdx.y;
    const float* src = Bw + (size_t)o * NTOT;
#pragma unroll
    for (int i = 0; i < 4; i++)
        tile[ty + i * 8][tx] = src[(size_t)(d0 + ty + i * 8) * HH + h0 + tx];
    __syncthreads();
    __half* dst = g_Bh + (size_t)o * NTOT;
#pragma unroll
    for (int i = 0; i < 4; i++)
        dst[(size_t)(h0 + ty + i * 8) * DD + d0 + tx] =
            __float2half_rn(tile[tx][ty + i * 8]);
}

// ===========================================================================
// Persistent HMMA V GEMM: V[m][o*256+h'] = sum_d x[m][d] * B_w[o][d][h']
// 148 persistent CTAs; tiles 256x128, BK=64; 4-stage cp.async ring that flows
// ACROSS tile boundaries (one pipeline fill per CTA, not per tile).
// ===========================================================================
#define VBM 256
#define VBN 128
#define ASTG (VBM * 128)          // 32 KB / stage
#define BSTG (VBN * 128)          // 16 KB / stage
#define STG  (ASTG + BSTG)        // 48 KB
#define VSMEM (4 * STG)           // 192 KB
#define VGRID 148
#define NTILES 16384              // (8192/256) * (65536/128)

__global__ void __launch_bounds__(256, 1) gemm_v_mma(void) {
    extern __shared__ char smem[];
    const uint32_t sb = smem_u32(smem);
    const int tid  = threadIdx.x;
    const int lane = tid & 31;
    const int w    = tid >> 5;
    const int bid  = blockIdx.x;

    const int wm = (w & 3) * 64;
    const int wn = (w >> 2) * 64;

    const int a_row = wm + (lane & 15);
    const int a_rx  = ((a_row & 7) * 16);
    const int a_xo  = ((lane >> 4) & 1) * 16;
    const int b_row = wn + (lane & 7) + ((lane >> 4) & 1) * 8;
    const int b_rx  = ((b_row & 7) * 16);
    const int b_xo  = ((lane >> 3) & 1) * 16;

    const int ntl = (NTILES - bid + VGRID - 1) / VGRID;
    const int Q   = ntl * 4;                 // total K-chunks for this CTA

    float acc[4][8][4];
#pragma unroll
    for (int i = 0; i < 4; i++)
#pragma unroll
        for (int j = 0; j < 8; j++)
#pragma unroll
            for (int e = 0; e < 4; e++) acc[i][j][e] = 0.f;

    auto load_chunk = [&](int q) {
        const int tq = q >> 2;
        const int gt = bid + tq * VGRID;
        const int m0 = (gt & 31) * VBM;
        const int n0 = (gt >> 5) * VBN;
        const int kc = q & 3;
        const uint32_t sA = sb + (q & 3) * STG;   // stage = q % 4
        const uint32_t sB = sA + ASTG;
        const __half* As  = g_xh + (size_t)m0 * DD + kc * 64;
        const __half* Bs2 = g_Bh + (size_t)n0 * DD + kc * 64;
#pragma unroll
        for (int i = 0; i < 8; i++) {
            const int idx = tid + 256 * i;
            const int r = idx >> 3, c = idx & 7;
            const uint32_t d = r * 128 + ((c * 16) ^ ((r & 7) * 16));
            cp16s(sA + d, As + (size_t)r * DD + c * 8);
        }
#pragma unroll
        for (int i = 0; i < 4; i++) {
            const int idx = tid + 256 * i;
            const int r = idx >> 3, c = idx & 7;
            const uint32_t d = r * 128 + ((c * 16) ^ ((r & 7) * 16));
            cp16s(sB + d, Bs2 + (size_t)r * DD + c * 8);
        }
        asm volatile("cp.async.commit_group;");
    };

    // prologue: 3 chunks in flight
    load_chunk(0);
    load_chunk(1);
    load_chunk(2);

#pragma unroll 1
    for (int q = 0; q < Q; q++) {
        if (q < Q - 2)      asm volatile("cp.async.wait_group 2;");
        else if (q < Q - 1) asm volatile("cp.async.wait_group 1;");
        else                asm volatile("cp.async.wait_group 0;");
        __syncthreads();
        if (q + 3 < Q) load_chunk(q + 3);

        const uint32_t sA = sb + (q & 3) * STG;
        const uint32_t sB = sA + ASTG;
#pragma unroll
        for (int ks = 0; ks < 4; ks++) {
            uint32_t afr[4][4], bfr[4][4];
#pragma unroll
            for (int mt = 0; mt < 4; mt++) {
                const int r = a_row + mt * 16;
                ldsm4(afr[mt], sA + r * 128 + ((ks * 32 + a_xo) ^ a_rx));
            }
#pragma unroll
            for (int nt2 = 0; nt2 < 4; nt2++) {
                const int r = b_row + nt2 * 16;
                ldsm4(bfr[nt2], sB + r * 128 + ((ks * 32 + b_xo) ^ b_rx));
            }
#pragma unroll
            for (int mt = 0; mt < 4; mt++)
#pragma unroll
                for (int nt = 0; nt < 8; nt++)
                    mma16816(acc[mt][nt], afr[mt], &bfr[nt >> 1][(nt & 1) * 2]);
        }

        if ((q & 3) == 3) {   // tile finished: epilogue + reset
            const int tq = q >> 2;
            const int gt = bid + tq * VGRID;
            const int m0 = (gt & 31) * VBM;
            const int n0 = (gt >> 5) * VBN;
            const int fr = lane >> 2, fq = (lane & 3) * 2;
#pragma unroll
            for (int mt = 0; mt < 4; mt++) {
                const int mA = m0 + wm + mt * 16 + fr;
#pragma unroll
                for (int nt = 0; nt < 8; nt++) {
                    const int col = n0 + wn + nt * 8 + fq;
                    *(__half2*)&g_Vh[(size_t)mA * NTOT + col] =
                        __floats2half2_rn(acc[mt][nt][0], acc[mt][nt][1]);
                    *(__half2*)&g_Vh[(size_t)(mA + 8) * NTOT + col] =
                        __floats2half2_rn(acc[mt][nt][2], acc[mt][nt][3]);
                    acc[mt][nt][0] = 0.f; acc[mt][nt][1] = 0.f;
                    acc[mt][nt][2] = 0.f; acc[mt][nt][3] = 0.f;
                }
            }
        }
    }
}

// ===========================================================================
// GEMM 2 (fp32 SIMT): Wx = x @ W^T + b  (unchanged, ~100us)
// ===========================================================================
__global__ __launch_bounds__(256) void gemm_wx_kernel(
    const float* __restrict__ A, const float* __restrict__ Ww,
    const float* __restrict__ Wb)
{
    __shared__ float As[2][16 * 132];
    __shared__ float Bs[2][16 * 132];
    const int tid = threadIdx.x;
    const int n0  = blockIdx.x * 128;
    const int m0  = blockIdx.y * 128;
    const int am = tid >> 1, ah = (tid & 1) * 8;
    const int tx = tid & 15, ty = tid >> 4;
    const float* Aptr = A  + (size_t)(m0 + am) * DD + ah;
    const float* Wptr = Ww + (size_t)(n0 + am) * DD + ah;

    float4 a0r = *(const float4*)(Aptr);
    float4 a1r = *(const float4*)(Aptr + 4);
    float4 b0r = *(const float4*)(Wptr);
    float4 b1r = *(const float4*)(Wptr + 4);

    float acc[8][8];
#pragma unroll
    for (int i = 0; i < 8; i++)
#pragma unroll
        for (int j = 0; j < 8; j++) acc[i][j] = 0.f;

    {
        float av[8] = {a0r.x,a0r.y,a0r.z,a0r.w,a1r.x,a1r.y,a1r.z,a1r.w};
        float bv[8] = {b0r.x,b0r.y,b0r.z,b0r.w,b1r.x,b1r.y,b1r.z,b1r.w};
#pragma unroll
        for (int i = 0; i < 8; i++) {
            As[0][(ah + i) * 132 + am] = av[i];
            Bs[0][(ah + i) * 132 + am] = bv[i];
        }
    }
    __syncthreads();

    int p = 0;
#pragma unroll 1
    for (int s = 0; s < 16; s++) {
        if (s < 15) {
            const int k0 = (s + 1) * 16;
            a0r = *(const float4*)(Aptr + k0);
            a1r = *(const float4*)(Aptr + k0 + 4);
            b0r = *(const float4*)(Wptr + k0);
            b1r = *(const float4*)(Wptr + k0 + 4);
        }
#pragma unroll
        for (int kk = 0; kk < 16; kk++) {
            float4 a0 = *(const float4*)&As[p][kk * 132 + ty * 4];
            float4 a1 = *(const float4*)&As[p][kk * 132 + 64 + ty * 4];
            float4 b0 = *(const float4*)&Bs[p][kk * 132 + tx * 4];
            float4 b1 = *(const float4*)&Bs[p][kk * 132 + 64 + tx * 4];
            float ar[8] = {a0.x,a0.y,a0.z,a0.w,a1.x,a1.y,a1.z,a1.w};
            float br[8] = {b0.x,b0.y,b0.z,b0.w,b1.x,b1.y,b1.z,b1.w};
#pragma unroll
            for (int i = 0; i < 8; i++)
#pragma unroll
                for (int j = 0; j < 8; j++) acc[i][j] += ar[i] * br[j];
        }
        if (s < 15) {
            __syncthreads();
            const int q = p ^ 1;
            float av[8] = {a0r.x,a0r.y,a0r.z,a0r.w,a1r.x,a1r.y,a1r.z,a1r.w};
            float bv[8] = {b0r.x,b0r.y,b0r.z,b0r.w,b1r.x,b1r.y,b1r.z,b1r.w};
#pragma unroll
            for (int i = 0; i < 8; i++) {
                As[q][(ah + i) * 132 + am] = av[i];
                Bs[q][(ah + i) * 132 + am] = bv[i];
            }
            __syncthreads();
            p = q;
        }
    }

    float wb0[4], wb1[4];
#pragma unroll
    for (int j = 0; j < 4; j++) {
        wb0[j] = Wb[n0 + tx * 4 + j];
        wb1[j] = Wb[n0 + 64 + tx * 4 + j];
    }
#pragma unroll
    for (int i = 0; i < 8; i++) {
        const int rr = (i < 4) ? (ty * 4 + i) : (64 + ty * 4 + (i - 4));
        float* Wo = g_Wx + (size_t)(m0 + rr) * GG + n0;
        *(float4*)&Wo[tx * 4] = make_float4(acc[i][0] + wb0[0], acc[i][1] + wb0[1],
                                            acc[i][2] + wb0[2], acc[i][3] + wb0[3]);
        *(float4*)&Wo[64 + tx * 4] = make_float4(acc[i][4] + wb1[0], acc[i][5] + wb1[1],
                                                 acc[i][6] + wb1[2], acc[i][7] + wb1[3]);
    }
}

// ===========================================================================
// Scan v4: R8 skeleton (DSMEM push + cluster barrier — the proven fast path)
// + multi-accumulator dot chains + top-of-step double-buffered V/wx prefetch.
// ===========================================================================
__global__ void __cluster_dims__(8, 1, 1) __launch_bounds__(512, 1)
scan_kernel(const float* __restrict__ Uw, const float* __restrict__ Ub,
            const float* __restrict__ Bbias, float* __restrict__ out)
{
    __shared__ float h_sm[2][HH];
    __shared__ float gates_sm[128];
    __shared__ float m_sm[32];
    __shared__ float c_sm[32];
    __shared__ float bb_sm[32];

    const int r     = blockIdx.x;
    const int b     = blockIdx.y;
    const int jbase = r * 32;
    const int t     = threadIdx.x;
    const int qt    = t & 3;
    const int lg    = t >> 2;
    const int row   = (lg >> 5) * HH + jbase + (lg & 31);
    const int r16   = t >> 4;
    const int l16   = t & 15;

    float4 U4[16];
#pragma unroll
    for (int i = 0; i < 16; i++)
        U4[i] = *(const float4*)&Uw[(size_t)row * HH + (size_t)(i * 4 + qt) * 4];
    const float ub = Ub[row];

    if (t < HH)  h_sm[0][t] = 0.f;
    if (t < 32) { c_sm[t] = 0.f; bb_sm[t] = Bbias[jbase + t]; }
    __syncthreads();

    const size_t vrow_off = (size_t)(jbase + r16) * HH + (size_t)l16 * 16;
    // current-step V and wx
    uint4 vc0 = *(const uint4*)(g_Vh + (size_t)(b * TT) * NTOT + vrow_off);
    uint4 vc1 = *(const uint4*)(g_Vh + (size_t)(b * TT) * NTOT + vrow_off + 8);
    float wx  = (qt == 0) ? g_Wx[(size_t)(b * TT) * GG + row] : 0.f;

    for (int step = 0; step < TT; step++) {
        const int p = step & 1;
        const float4* h4 = (const float4*)h_sm[p];
        const int mrow = b * TT + step;
        const int nrow = (step + 1 < TT) ? (mrow + 1) : mrow;

        // ---- top-of-step prefetch for step+1 (h-independent, max distance) --
        uint4 vn0 = *(const uint4*)(g_Vh + (size_t)nrow * NTOT + vrow_off);
        uint4 vn1 = *(const uint4*)(g_Vh + (size_t)nrow * NTOT + vrow_off + 8);
        float wxn = (qt == 0) ? g_Wx[(size_t)nrow * GG + row] : 0.f;

        // ---- gates: dot(U_row, h), 4 independent accumulator chains ----
        float ac0 = 0.f, ac1 = 0.f, ac2 = 0.f, ac3 = 0.f;
#pragma unroll
        for (int i = 0; i < 4; i++) {
            float4 h0 = h4[(i * 4 + 0) * 4 + qt];
            float4 u0 = U4[i * 4 + 0];
            ac0 += h0.x * u0.x + h0.y * u0.y + h0.z * u0.z + h0.w * u0.w;
            float4 h1 = h4[(i * 4 + 1) * 4 + qt];
            float4 u1 = U4[i * 4 + 1];
            ac1 += h1.x * u1.x + h1.y * u1.y + h1.z * u1.z + h1.w * u1.w;
            float4 h2 = h4[(i * 4 + 2) * 4 + qt];
            float4 u2 = U4[i * 4 + 2];
            ac2 += h2.x * u2.x + h2.y * u2.y + h2.z * u2.z + h2.w * u2.w;
            float4 h3 = h4[(i * 4 + 3) * 4 + qt];
            float4 u3 = U4[i * 4 + 3];
            ac3 += h3.x * u3.x + h3.y * u3.y + h3.z * u3.z + h3.w * u3.w;
        }
        float acc = (ac0 + ac1) + (ac2 + ac3);
        acc += __shfl_xor_sync(0xffffffffu, acc, 1);
        acc += __shfl_xor_sync(0xffffffffu, acc, 2);

        // ---- m: dot(V_row fp16, h), 2 accumulator chains ----
        float ma = 0.f, mb2 = 0.f;
        {
            const __half2* vh0 = (const __half2*)&vc0;
            const __half2* vh1 = (const __half2*)&vc1;
            float4 ha  = h4[l16 * 4 + 0];
            float4 hbv = h4[l16 * 4 + 1];
            float4 hc  = h4[l16 * 4 + 2];
            float4 hd  = h4[l16 * 4 + 3];
            float2 pp;
            pp = __half22float2(vh0[0]); ma  += pp.x * ha.x  + pp.y * ha.y;
            pp = __half22float2(vh0[1]); mb2 += pp.x * ha.z  + pp.y * ha.w;
            pp = __half22float2(vh0[2]); ma  += pp.x * hbv.x + pp.y * hbv.y;
            pp = __half22float2(vh0[3]); mb2 += pp.x * hbv.z + pp.y * hbv.w;
            pp = __half22float2(vh1[0]); ma  += pp.x * hc.x  + pp.y * hc.y;
            pp = __half22float2(vh1[1]); mb2 += pp.x * hc.z  + pp.y * hc.w;
            pp = __half22float2(vh1[2]); ma  += pp.x * hd.x  + pp.y * hd.y;
            pp = __half22float2(vh1[3]); mb2 += pp.x * hd.z  + pp.y * hd.w;
        }
        float macc = ma + mb2;
#pragma unroll
        for (int off = 8; off > 0; off >>= 1)
            macc += __shfl_xor_sync(0xffffffffu, macc, off);

        if (qt == 0)  gates_sm[lg] = acc + wx + ub;
        if (l16 == 0) m_sm[r16] = macc;
        __syncthreads();

        if (t < 32) {
            const int j = jbase + t;
            const float iv = fsigm(gates_sm[t]);
            const float fv = fsigm(gates_sm[32 + t]);
            const float ov = fsigm(gates_sm[64 + t]);
            const float gv = ftanh(gates_sm[96 + t]);
            const float mv = ftanh(m_sm[t] + bb_sm[t]);
            const float c  = fv * c_sm[t] + iv * gv + SCALE_ * mv;
            c_sm[t] = c;
            const float hn = ov * ftanh(c);
            out[((size_t)b * TT + step) * HH + j] = hn;
            if (step == TT - 1) {
                const size_t base = (size_t)BB * TT * HH;
                out[base + (size_t)b * HH + j] = hn;
                out[base + (size_t)BB * HH + (size_t)b * HH + j] = c;
            }
            // push hn into next-step buffer of all 8 cluster CTAs
            const uint32_t la = smem_u32(&h_sm[p ^ 1][j]);
#pragma unroll
            for (int k = 0; k < 8; k++) ST_CL_F32(la, k, hn);
        }

        // cluster handoff (release/acquire orders DSMEM stores); wait doubles
        // as the CTA barrier for the next step's h reads.
        asm volatile("barrier.cluster.arrive.aligned;" ::: "memory");
        asm volatile("barrier.cluster.wait.aligned;"   ::: "memory");

        vc0 = vn0; vc1 = vn1; wx = wxn;
    }
}

// ===========================================================================
// Launcher
// ===========================================================================
extern "C" void kernel_launch(void* const* d_in, const int* in_sizes, int n_in,
                              void* d_out, int out_size)
{
    (void)in_sizes; (void)n_in; (void)out_size;
    const float* x   = (const float*)d_in[0];
    const float* Ww  = (const float*)d_in[1];
    const float* Wb  = (const float*)d_in[2];
    const float* Uw  = (const float*)d_in[3];
    const float* Ub  = (const float*)d_in[4];
    const float* Bw  = (const float*)d_in[5];
    const float* Bb  = (const float*)d_in[6];
    float* out = (float*)d_out;

    cudaFuncSetAttribute(gemm_v_mma,
                         cudaFuncAttributeMaxDynamicSharedMemorySize, VSMEM);

    conv_x_kernel<<<1024, 256>>>((const float2*)x);
    transB_kernel<<<dim3(8, 8, 256), dim3(32, 8)>>>(Bw);
    gemm_wx_kernel<<<dim3(GG / 128, (BB * TT) / 128), 256>>>(x, Ww, Wb);
    gemm_v_mma<<<VGRID, 256, VSMEM>>>();
    scan_kernel<<<dim3(8, BB), 512>>>(Uw, Ub, Bb, out);
}